// round 2
// baseline (speedup 1.0000x reference)
#include <cuda_runtime.h>
#include <cuda_bf16.h>
#include <cstdint>

// Problem dims (fixed by the dataset)
#define B_ROWS 65536
#define F_DIM  256
#define U_DIM  1024

// GEMM tiling
#define BM 128
#define BN 128
#define BK 64                     // 64 bf16 = 128B row (swizzle atom)
#define KITERS (F_DIM / BK)       // 4
#define NTHREADS 256

// Stage sizes in dynamic smem: A[2][128][64]bf16, B[2][128][64]bf16 = 64KB
#define STG_BYTES 16384
#define A_OFF 0
#define B_OFF 32768
#define SMEM_BYTES 65536

// device-global scratch (allocations are forbidden)
__device__ __nv_bfloat16 g_xb[(size_t)B_ROWS * F_DIM];  // x in bf16, row-major [B,F]
__device__ __nv_bfloat16 g_wt[(size_t)U_DIM * F_DIM];   // w transposed bf16 [U,F]
__device__ float g_wsq[U_DIM];
__device__ float g_xsq[B_ROWS];

// ---------------- PTX helpers ----------------
__device__ __forceinline__ uint32_t smem_u32(const void* p) {
    uint32_t a;
    asm("{ .reg .u64 t; cvta.to.shared.u64 t, %1; cvt.u32.u64 %0, t; }" : "=r"(a) : "l"(p));
    return a;
}
__device__ __forceinline__ void cp_async16(uint32_t dst, const void* src) {
    asm volatile("cp.async.cg.shared.global [%0], [%1], 16;" :: "r"(dst), "l"(src));
}
__device__ __forceinline__ void cp_commit() {
    asm volatile("cp.async.commit_group;" ::: "memory");
}
template<int N>
__device__ __forceinline__ void cp_wait() {
    asm volatile("cp.async.wait_group %0;" :: "n"(N) : "memory");
}
__device__ __forceinline__ uint32_t lds32(uint32_t addr) {
    uint32_t v;
    asm volatile("ld.shared.b32 %0, [%1];" : "=r"(v) : "r"(addr));
    return v;
}
__device__ __forceinline__ void mma_bf16(float* c, const uint32_t* a, const uint32_t* b) {
    asm volatile(
        "mma.sync.aligned.m16n8k16.row.col.f32.bf16.bf16.f32 "
        "{%0,%1,%2,%3}, {%4,%5,%6,%7}, {%8,%9}, {%0,%1,%2,%3};"
        : "+f"(c[0]), "+f"(c[1]), "+f"(c[2]), "+f"(c[3])
        : "r"(a[0]), "r"(a[1]), "r"(a[2]), "r"(a[3]), "r"(b[0]), "r"(b[1]));
}
__device__ __forceinline__ uint32_t pack_bf16x2(float lo, float hi) {
    __nv_bfloat162 h = __floats2bfloat162_rn(lo, hi);  // .x = lo (low half)
    return *reinterpret_cast<uint32_t*>(&h);
}

// ---------------- prologue kernels ----------------
// Transpose w [F,U] fp32 -> g_wt [U,F] bf16, and compute g_wsq[u] = sum_f w^2.
__global__ void wprep_kernel(const float* __restrict__ w) {
    int u = blockIdx.x;
    int f = threadIdx.x;  // 256 threads
    float v = w[(size_t)f * U_DIM + u];
    g_wt[(size_t)u * F_DIM + f] = __float2bfloat16(v);
    __shared__ float red[256];
    red[f] = v * v;
    __syncthreads();
    for (int s = 128; s > 0; s >>= 1) {
        if (f < s) red[f] += red[f + s];
        __syncthreads();
    }
    if (f == 0) g_wsq[u] = red[0];
}

// Convert x -> bf16 and compute g_xsq[b] = sum_f x^2. One warp per row.
__global__ void xprep_kernel(const float* __restrict__ x) {
    int row = blockIdx.x * 8 + (threadIdx.x >> 5);
    int lid = threadIdx.x & 31;
    const float4* xr = (const float4*)(x + (size_t)row * F_DIM);
    float4 a = xr[lid];         // cols 4*lid .. 4*lid+3
    float4 b = xr[lid + 32];    // cols 128+4*lid ..
    float s = a.x * a.x + a.y * a.y + a.z * a.z + a.w * a.w +
              b.x * b.x + b.y * b.y + b.z * b.z + b.w * b.w;
    #pragma unroll
    for (int o = 16; o; o >>= 1) s += __shfl_xor_sync(0xffffffffu, s, o);
    if (lid == 0) g_xsq[row] = s;

    uint32_t* dst = (uint32_t*)(g_xb + (size_t)row * F_DIM);
    dst[2 * lid + 0]  = pack_bf16x2(a.x, a.y);
    dst[2 * lid + 1]  = pack_bf16x2(a.z, a.w);
    dst[64 + 2 * lid] = pack_bf16x2(b.x, b.y);
    dst[65 + 2 * lid] = pack_bf16x2(b.z, b.w);
}

// ---------------- main GEMM kernel ----------------
// out[m,n] = xsq[m] + wsq[n] - 2 * sum_k xb[m,k]*wt[n,k]
// Swizzle: 128B rows of 8 16B-chunks; chunk c of row r stored at (c ^ (r&7)).
// Fragment LDS of (row, elem-col e): byteoff = 2e -> chunk = e>>3, inchunk = (2e)&15.
__global__ void __launch_bounds__(NTHREADS, 2) rbf_gemm(float* __restrict__ out) {
    extern __shared__ char smem[];
    uint32_t sb = smem_u32(smem);

    int tid = threadIdx.x;
    int wid = tid >> 5, lid = tid & 31;
    int g = lid >> 2, t = lid & 3;           // mma group / thread-in-group
    int wm = wid >> 2, wn = wid & 3;         // 2 x 4 warp grid; warp tile 64x32
    int m0 = blockIdx.y * BM;
    int n0 = blockIdx.x * BN;

    const __nv_bfloat16* xa = g_xb + (size_t)m0 * F_DIM;
    const __nv_bfloat16* wb = g_wt + (size_t)n0 * F_DIM;

    float acc[4][4][4];
    #pragma unroll
    for (int i = 0; i < 4; ++i)
        #pragma unroll
        for (int j = 0; j < 4; ++j)
            #pragma unroll
            for (int q = 0; q < 4; ++q) acc[i][j][q] = 0.0f;

    // stage loader: 1024 16B-chunks each for A and B; 4 per thread per tile
    auto load_stage = [&](int stage, int kt) {
        #pragma unroll
        for (int r = 0; r < 4; ++r) {
            int chunk = tid + r * 256;
            int row = chunk >> 3, c = chunk & 7;
            uint32_t dst = sb + A_OFF + stage * STG_BYTES + row * 128 + ((c ^ (row & 7)) << 4);
            cp_async16(dst, xa + (size_t)row * F_DIM + kt * BK + c * 8);
        }
        #pragma unroll
        for (int r = 0; r < 4; ++r) {
            int chunk = tid + r * 256;
            int row = chunk >> 3, c = chunk & 7;
            uint32_t dst = sb + B_OFF + stage * STG_BYTES + row * 128 + ((c ^ (row & 7)) << 4);
            cp_async16(dst, wb + (size_t)row * F_DIM + kt * BK + c * 8);
        }
        cp_commit();
    };

    load_stage(0, 0);
    load_stage(1, 1);

    #pragma unroll
    for (int kt = 0; kt < KITERS; ++kt) {
        int s = kt & 1;
        if (kt == KITERS - 1) cp_wait<0>(); else cp_wait<1>();
        __syncthreads();

        uint32_t a_base = sb + A_OFF + s * STG_BYTES;
        uint32_t b_base = sb + B_OFF + s * STG_BYTES;

        #pragma unroll
        for (int ks = 0; ks < 4; ++ks) {   // four k16 steps per BK=64 tile
            uint32_t a[4][4];
            uint32_t b[4][2];
            #pragma unroll
            for (int i = 0; i < 4; ++i) {
                int rlo = wm * 64 + i * 16 + g;
                int rhi = rlo + 8;
                uint32_t c0 = 2 * ks, c1 = 2 * ks + 1;
                a[i][0] = lds32(a_base + rlo * 128 + ((c0 ^ (rlo & 7)) << 4) + 4 * t);
                a[i][1] = lds32(a_base + rhi * 128 + ((c0 ^ (rhi & 7)) << 4) + 4 * t);
                a[i][2] = lds32(a_base + rlo * 128 + ((c1 ^ (rlo & 7)) << 4) + 4 * t);
                a[i][3] = lds32(a_base + rhi * 128 + ((c1 ^ (rhi & 7)) << 4) + 4 * t);
            }
            #pragma unroll
            for (int j = 0; j < 4; ++j) {
                int nr = wn * 32 + j * 8 + g;
                uint32_t c0 = 2 * ks, c1 = 2 * ks + 1;
                b[j][0] = lds32(b_base + nr * 128 + ((c0 ^ (nr & 7)) << 4) + 4 * t);
                b[j][1] = lds32(b_base + nr * 128 + ((c1 ^ (nr & 7)) << 4) + 4 * t);
            }
            #pragma unroll
            for (int i = 0; i < 4; ++i)
                #pragma unroll
                for (int j = 0; j < 4; ++j)
                    mma_bf16(acc[i][j], a[i], b[j]);
        }
        __syncthreads();
        if (kt + 2 < KITERS) load_stage(s, kt + 2);
    }

    // fused epilogue: out = xsq + wsq - 2*cross, float2 stores
    #pragma unroll
    for (int i = 0; i < 4; ++i) {
        int mlo = m0 + wm * 64 + i * 16 + g;
        int mhi = mlo + 8;
        float xlo = g_xsq[mlo];
        float xhi = g_xsq[mhi];
        #pragma unroll
        for (int j = 0; j < 4; ++j) {
            int n = n0 + wn * 32 + j * 8 + 2 * t;
            float2 ws = *(const float2*)(g_wsq + n);
            float2 olo, ohi;
            olo.x = fmaf(-2.0f, acc[i][j][0], xlo + ws.x);
            olo.y = fmaf(-2.0f, acc[i][j][1], xlo + ws.y);
            ohi.x = fmaf(-2.0f, acc[i][j][2], xhi + ws.x);
            ohi.y = fmaf(-2.0f, acc[i][j][3], xhi + ws.y);
            *(float2*)(out + (size_t)mlo * U_DIM + n) = olo;
            *(float2*)(out + (size_t)mhi * U_DIM + n) = ohi;
        }
    }
}

// ---------------- host launch ----------------
extern "C" void kernel_launch(void* const* d_in, const int* in_sizes, int n_in,
                              void* d_out, int out_size) {
    const float* x = (const float*)d_in[0];
    const float* w = (const float*)d_in[1];
    float* out = (float*)d_out;

    wprep_kernel<<<U_DIM, 256>>>(w);
    xprep_kernel<<<B_ROWS / 8, 256>>>(x);

    static int smem_set = 0;
    if (!smem_set) {
        cudaFuncSetAttribute(rbf_gemm, cudaFuncAttributeMaxDynamicSharedMemorySize, SMEM_BYTES);
        smem_set = 1;
    }
    dim3 grid(U_DIM / BN, B_ROWS / BM);  // (8, 512): n-tiles adjacent for x reuse in L2
    rbf_gemm<<<grid, NTHREADS, SMEM_BYTES>>>(out);
}